// round 2
// baseline (speedup 1.0000x reference)
#include <cuda_runtime.h>

#define B_    512
#define HW_   128
#define C1_   32
#define C2_   64

typedef unsigned long long u64;

// Intermediate h: [512, 32, 64, 64] fp32 = 256 MB (static __device__, no alloc)
__device__ float g_h[(size_t)B_ * C1_ * 64 * 64];

// ---- packed f32x2 helpers ------------------------------------------------
__device__ __forceinline__ u64 pk2(float lo, float hi) {
    u64 r; asm("mov.b64 %0, {%1, %2};" : "=l"(r) : "f"(lo), "f"(hi)); return r;
}
__device__ __forceinline__ void fma2(u64& d, u64 a, u64 b) {
    asm("fma.rn.f32x2 %0, %1, %2, %0;" : "+l"(d) : "l"(a), "l"(b));
}
__device__ __forceinline__ void upk2(u64 v, float& lo, float& hi) {
    asm("mov.b64 {%0, %1}, %2;" : "=f"(lo), "=f"(hi) : "l"(v));
}

// ---------------------------------------------------------------------------
// Kernel 1: Conv(3->32, k3, s1, p1) + bias + BN + ReLU + MaxPool2
// Grid (4, 4, 512), 256 thr. Each thread: one pooled pixel, all 32 oc.
// f32x2: horizontal conv-output pairs; weights duplicated (w,w) in smem.
// ---------------------------------------------------------------------------
__global__ void __launch_bounds__(256) conv1_fused(
    const float* __restrict__ crops,
    const float* __restrict__ w1, const float* __restrict__ b1,
    const float* __restrict__ g1, const float* __restrict__ be1,
    const float* __restrict__ m1, const float* __restrict__ v1)
{
    __shared__ float s_in[3][34][35];     // +1 col pad
    __shared__ u64   s_w[C1_ * 27];       // (w,w) duplicated pairs
    __shared__ float s_scale[C1_], s_bias[C1_];

    const int b   = blockIdx.z;
    const int cx0 = blockIdx.x * 32;
    const int cy0 = blockIdx.y * 32;
    const int t   = threadIdx.x;

    for (int i = t; i < C1_ * 27; i += 256) { float w = w1[i]; s_w[i] = pk2(w, w); }
    if (t < C1_) {
        float inv = g1[t] * rsqrtf(v1[t] + 1e-5f);
        s_scale[t] = inv;
        s_bias[t]  = be1[t] + (b1[t] - m1[t]) * inv;
    }

    const float* cb = crops + (size_t)b * 3 * HW_ * HW_;
    for (int i = t; i < 3 * 34 * 34; i += 256) {
        int ci = i / (34 * 34);
        int rem = i % (34 * 34);
        int r = rem / 34, c = rem % 34;
        int gr = cy0 - 1 + r, gc = cx0 - 1 + c;
        float v = 0.f;
        if (gr >= 0 && gr < HW_ && gc >= 0 && gc < HW_)
            v = cb[ci * HW_ * HW_ + gr * HW_ + gc];
        s_in[ci][r][c] = v;
    }
    __syncthreads();

    const int px = t & 15, py = t >> 4;

    // Input pairs: P[ci][r][kx] = (p[r][kx], p[r][kx+1]),  r=0..3, kx=0..2
    u64 P[3][4][3];
#pragma unroll
    for (int ci = 0; ci < 3; ci++)
#pragma unroll
        for (int r = 0; r < 4; r++) {
            float x0 = s_in[ci][2 * py + r][2 * px + 0];
            float x1 = s_in[ci][2 * py + r][2 * px + 1];
            float x2 = s_in[ci][2 * py + r][2 * px + 2];
            float x3 = s_in[ci][2 * py + r][2 * px + 3];
            P[ci][r][0] = pk2(x0, x1);
            P[ci][r][1] = pk2(x1, x2);
            P[ci][r][2] = pk2(x2, x3);
        }

    float* hb = g_h + (size_t)b * C1_ * 64 * 64;
    const int oy = blockIdx.y * 16 + py;
    const int ox = blockIdx.x * 16 + px;

    for (int oc = 0; oc < C1_; oc++) {
        u64 A0 = 0ull, A1 = 0ull;     // (a00,a01), (a10,a11)
        const u64* w = &s_w[oc * 27];
#pragma unroll
        for (int ci = 0; ci < 3; ci++)
#pragma unroll
            for (int ky = 0; ky < 3; ky++)
#pragma unroll
                for (int kx = 0; kx < 3; kx++) {
                    u64 W = w[ci * 9 + ky * 3 + kx];
                    fma2(A0, P[ci][ky    ][kx], W);
                    fma2(A1, P[ci][ky + 1][kx], W);
                }
        float a00, a01, a10, a11;
        upk2(A0, a00, a01);
        upk2(A1, a10, a11);
        float sc = s_scale[oc], bi = s_bias[oc];
        float mv = fmaxf(fmaxf(a00, a01), fmaxf(a10, a11));
        mv = fmaxf(mv * sc + bi, bi * 0.f);          // affine of max (sc>0: gamma*rsqrt>0? not guaranteed)
        // NOTE: gamma is uniform(0,1) > 0, so scale > 0 and affine commutes with max.
        mv = fmaxf(mv, 0.f);                          // ReLU commutes with max
        hb[oc * 64 * 64 + oy * 64 + ox] = mv;
    }
}

// ---------------------------------------------------------------------------
// Kernel 2: Conv(32->64, k3, s2, p1) + bias + BN + Sigmoid + MaxPool2
// Grid (2, 2, 512), 512 thr: pix = t&63 (8x8 pooled), grp = t>>6 (8 oc each).
// f32x2: horizontal conv-output pairs (stride-2 -> input pair (kx, kx+2)).
// ---------------------------------------------------------------------------
__global__ void __launch_bounds__(512) conv2_fused(
    const float* __restrict__ w2, const float* __restrict__ b2,
    const float* __restrict__ g2, const float* __restrict__ be2,
    const float* __restrict__ m2, const float* __restrict__ v2,
    float* __restrict__ feat)
{
    __shared__ float s_in[4][33][34];     // +1 col pad  (17.95 KB)
    __shared__ u64   s_w[C2_ * 4 * 9];    // dup pairs, chunk of 4 in-ch (18.4 KB)
    __shared__ float s_scale[C2_], s_bias[C2_];

    const int b  = blockIdx.z;
    const int bx = blockIdx.x, by = blockIdx.y;
    const int t  = threadIdx.x;

    if (t < C2_) {
        float inv = g2[t] * rsqrtf(v2[t] + 1e-5f);
        s_scale[t] = inv;
        s_bias[t]  = be2[t] + (b2[t] - m2[t]) * inv;
    }

    const int pix = t & 63, grp = t >> 6;     // grp 0..7 -> 8 oc each
    const int px = pix & 7, py = pix >> 3;

    u64 acc[8][2];                            // [oc][row-pair], each (col0,col1)
#pragma unroll
    for (int i = 0; i < 8; i++) { acc[i][0] = 0ull; acc[i][1] = 0ull; }

    const float* hb = g_h + (size_t)b * C1_ * 64 * 64;
    const int r0 = 32 * by - 1;
    const int c0 = 32 * bx - 1;

    for (int cc = 0; cc < 8; cc++) {          // 8 chunks of 4 input channels
        __syncthreads();
        for (int i = t; i < C2_ * 36; i += 512) {
            int oc = i / 36, rem = i % 36;
            int cil = rem / 9, k = rem % 9;
            float w = w2[oc * C1_ * 9 + (cc * 4 + cil) * 9 + k];
            s_w[i] = pk2(w, w);
        }
        for (int i = t; i < 4 * 33 * 33; i += 512) {
            int cil = i / (33 * 33);
            int rem = i % (33 * 33);
            int r = rem / 33, c = rem % 33;
            int gr = r0 + r, gc = c0 + c;
            float v = 0.f;
            if (gr >= 0 && gr < 64 && gc >= 0 && gc < 64)
                v = hb[(cc * 4 + cil) * 64 * 64 + gr * 64 + gc];
            s_in[cil][r][c] = v;
        }
        __syncthreads();

#pragma unroll
        for (int cil = 0; cil < 4; cil++) {
            // 5x5 patch -> pairs P[r][kx] = (p[r][kx], p[r][kx+2])
            float p[5][5];
#pragma unroll
            for (int r = 0; r < 5; r++)
#pragma unroll
                for (int c = 0; c < 5; c++)
                    p[r][c] = s_in[cil][4 * py + r][4 * px + c];

            u64 P[5][3];
#pragma unroll
            for (int r = 0; r < 5; r++) {
                P[r][0] = pk2(p[r][0], p[r][2]);
                P[r][1] = pk2(p[r][1], p[r][3]);
                P[r][2] = pk2(p[r][2], p[r][4]);
            }

#pragma unroll
            for (int oc = 0; oc < 8; oc++) {
                const u64* w = &s_w[((grp * 8 + oc) * 4 + cil) * 9];
#pragma unroll
                for (int ky = 0; ky < 3; ky++)
#pragma unroll
                    for (int kx = 0; kx < 3; kx++) {
                        u64 W = w[ky * 3 + kx];
                        fma2(acc[oc][0], P[ky    ][kx], W);
                        fma2(acc[oc][1], P[ky + 2][kx], W);
                    }
            }
        }
    }

    // Epilogue: max-pool -> affine -> sigmoid (scale>0 since gamma~U(0,1))
    const int oy = by * 8 + py, ox = bx * 8 + px;
    float* fb = feat + (size_t)b * C2_ * 16 * 16;
#pragma unroll
    for (int oc = 0; oc < 8; oc++) {
        int c = grp * 8 + oc;
        float v00, v01, v10, v11;
        upk2(acc[oc][0], v00, v01);
        upk2(acc[oc][1], v10, v11);
        float sc = s_scale[c], bi = s_bias[c];
        float m = fmaxf(fmaxf(v00, v01), fmaxf(v10, v11));
        float v = m * sc + bi;
        float sig = 1.f / (1.f + __expf(-v));
        fb[c * 256 + oy * 16 + ox] = sig;
    }
}

// ---------------------------------------------------------------------------
// Kernel 3: per-image mean over feat [64,16,16] -> scores + detected
// ---------------------------------------------------------------------------
__global__ void __launch_bounds__(256) score_reduce(
    const float* __restrict__ feat,
    float* __restrict__ scores,
    float* __restrict__ detected)
{
    const int b = blockIdx.x;
    const float* fb = feat + (size_t)b * 16384;
    float s = 0.f;
    for (int i = threadIdx.x; i < 16384; i += 256) s += fb[i];

    __shared__ float red[8];
#pragma unroll
    for (int o = 16; o > 0; o >>= 1) s += __shfl_down_sync(0xffffffffu, s, o);
    if ((threadIdx.x & 31) == 0) red[threadIdx.x >> 5] = s;
    __syncthreads();
    if (threadIdx.x < 8) {
        s = red[threadIdx.x];
#pragma unroll
        for (int o = 4; o > 0; o >>= 1) s += __shfl_down_sync(0xffu, s, o);
        if (threadIdx.x == 0) {
            float sc = s * (1.f / 16384.f);
            scores[b]   = sc;
            detected[b] = (sc >= 0.55f) ? 1.f : 0.f;
        }
    }
}

// ---------------------------------------------------------------------------
extern "C" void kernel_launch(void* const* d_in, const int* in_sizes, int n_in,
                              void* d_out, int out_size)
{
    const float* crops = (const float*)d_in[0];
    const float* w1  = (const float*)d_in[1];
    const float* b1  = (const float*)d_in[2];
    const float* g1  = (const float*)d_in[3];
    const float* be1 = (const float*)d_in[4];
    const float* m1  = (const float*)d_in[5];
    const float* v1  = (const float*)d_in[6];
    const float* w2  = (const float*)d_in[7];
    const float* b2  = (const float*)d_in[8];
    const float* g2  = (const float*)d_in[9];
    const float* be2 = (const float*)d_in[10];
    const float* m2  = (const float*)d_in[11];
    const float* v2  = (const float*)d_in[12];

    float* out      = (float*)d_out;
    float* feat     = out;                                   // 512*64*16*16
    float* scores   = out + (size_t)B_ * C2_ * 16 * 16;      // +512
    float* detected = scores + B_;                           // +512

    conv1_fused<<<dim3(4, 4, B_), 256>>>(crops, w1, b1, g1, be1, m1, v1);
    conv2_fused<<<dim3(2, 2, B_), 512>>>(w2, b2, g2, be2, m2, v2, feat);
    score_reduce<<<B_, 256>>>(feat, scores, detected);
}

// round 3
// speedup vs baseline: 1.1485x; 1.1485x over previous
#include <cuda_runtime.h>

#define B_    512
#define HW_   128
#define C1_   32
#define C2_   64

// Intermediate h: [512, 32, 64, 64] fp32 = 256 MB (static __device__, no alloc)
__device__ float g_h[(size_t)B_ * C1_ * 64 * 64];

// ---------------------------------------------------------------------------
// Kernel 1: Conv(3->32, k3, s1, p1) + bias + BN + ReLU + MaxPool2
// Grid (4, 4, 512), 256 thr. Each thread: one pooled pixel, all 32 oc.
// Weights pre-scaled by BN scale, padded rows of 4 -> LDS.128.
// ---------------------------------------------------------------------------
__global__ void __launch_bounds__(256) conv1_fused(
    const float* __restrict__ crops,
    const float* __restrict__ w1, const float* __restrict__ b1,
    const float* __restrict__ g1, const float* __restrict__ be1,
    const float* __restrict__ m1, const float* __restrict__ v1)
{
    __shared__ float s_in[3][34][36];          // stride 36 (8/16B friendly)
    __shared__ __align__(16) float s_w[C1_ * 36];  // [oc][ci][ky][4] pre-scaled
    __shared__ float s_scale[C1_], s_bias[C1_];

    const int b   = blockIdx.z;
    const int cx0 = blockIdx.x * 32;
    const int cy0 = blockIdx.y * 32;
    const int t   = threadIdx.x;

    if (t < C1_) {
        float inv = g1[t] * rsqrtf(v1[t] + 1e-5f);
        s_scale[t] = inv;
        s_bias[t]  = be1[t] + (b1[t] - m1[t]) * inv;   // conv pre-scaled => add bias only
    }

    const float* cb = crops + (size_t)b * 3 * HW_ * HW_;
    for (int i = t; i < 3 * 34 * 34; i += 256) {
        int ci = i / (34 * 34);
        int rem = i % (34 * 34);
        int r = rem / 34, c = rem % 34;
        int gr = cy0 - 1 + r, gc = cx0 - 1 + c;
        float v = 0.f;
        if (gr >= 0 && gr < HW_ && gc >= 0 && gc < HW_)
            v = cb[ci * HW_ * HW_ + gr * HW_ + gc];
        s_in[ci][r][c] = v;
    }
    __syncthreads();   // s_scale ready (and s_in)

    // weights: pre-scaled, padded kx 3->4
    for (int i = t; i < C1_ * 27; i += 256) {
        int oc = i / 27, k = i % 27;
        int ci = k / 9, ky = (k % 9) / 3, kx = k % 3;
        s_w[oc * 36 + ci * 12 + ky * 4 + kx] = w1[i] * s_scale[oc];
    }
    __syncthreads();

    const int px = t & 15, py = t >> 4;

    // Register patch: 3 ch x 4x4 via LDS.64 pairs (2*px is even)
    float p[3][4][4];
#pragma unroll
    for (int ci = 0; ci < 3; ci++)
#pragma unroll
        for (int r = 0; r < 4; r++) {
            float2 a = *(const float2*)&s_in[ci][2 * py + r][2 * px];
            float2 c2 = *(const float2*)&s_in[ci][2 * py + r][2 * px + 2];
            p[ci][r][0] = a.x;  p[ci][r][1] = a.y;
            p[ci][r][2] = c2.x; p[ci][r][3] = c2.y;
        }

    float* hb = g_h + (size_t)b * C1_ * 64 * 64;
    const int oy = blockIdx.y * 16 + py;
    const int ox = blockIdx.x * 16 + px;

    for (int oc = 0; oc < C1_; oc++) {
        float a00 = 0.f, a01 = 0.f, a10 = 0.f, a11 = 0.f;
        const float4* w4 = (const float4*)&s_w[oc * 36];
#pragma unroll
        for (int ci = 0; ci < 3; ci++)
#pragma unroll
            for (int ky = 0; ky < 3; ky++) {
                float4 w = w4[ci * 3 + ky];     // LDS.128: (w0,w1,w2,pad)
                a00 = fmaf(p[ci][ky    ][0], w.x, a00);
                a01 = fmaf(p[ci][ky    ][1], w.x, a01);
                a10 = fmaf(p[ci][ky + 1][0], w.x, a10);
                a11 = fmaf(p[ci][ky + 1][1], w.x, a11);
                a00 = fmaf(p[ci][ky    ][1], w.y, a00);
                a01 = fmaf(p[ci][ky    ][2], w.y, a01);
                a10 = fmaf(p[ci][ky + 1][1], w.y, a10);
                a11 = fmaf(p[ci][ky + 1][2], w.y, a11);
                a00 = fmaf(p[ci][ky    ][2], w.z, a00);
                a01 = fmaf(p[ci][ky    ][3], w.z, a01);
                a10 = fmaf(p[ci][ky + 1][2], w.z, a10);
                a11 = fmaf(p[ci][ky + 1][3], w.z, a11);
            }
        // conv already BN-scaled; max-pool -> +bias -> ReLU (all commute, scale>0)
        float mv = fmaxf(fmaxf(a00, a01), fmaxf(a10, a11)) + s_bias[oc];
        hb[oc * 64 * 64 + oy * 64 + ox] = fmaxf(mv, 0.f);
    }
}

// ---------------------------------------------------------------------------
// Kernel 2: Conv(32->64, k3, s2, p1) + bias + BN + Sigmoid + MaxPool2
// Grid (2, 2, 512), 256 thr: pix = t&63? no -- 256 thr: pix=t&63, grp=t>>6,
// 16 oc per thread (full-unrolled so accs stay in regs).
// Weights pre-scaled by BN scale, padded to [oc][cil][ky][4] -> LDS.128.
// ---------------------------------------------------------------------------
__global__ void __launch_bounds__(256) conv2_fused(
    const float* __restrict__ w2, const float* __restrict__ b2,
    const float* __restrict__ g2, const float* __restrict__ be2,
    const float* __restrict__ m2, const float* __restrict__ v2,
    float* __restrict__ feat)
{
    __shared__ float s_in[4][33][36];              // 19.0 KB, stride 36
    __shared__ __align__(16) float s_w[C2_ * 48];  // [oc][cil][ky][4]  12.3 KB
    __shared__ float s_scale[C2_], s_bias[C2_];

    const int b  = blockIdx.z;
    const int bx = blockIdx.x, by = blockIdx.y;
    const int t  = threadIdx.x;

    if (t < C2_) {
        float inv = g2[t] * rsqrtf(v2[t] + 1e-5f);
        s_scale[t] = inv;
        s_bias[t]  = be2[t] + (b2[t] - m2[t]) * inv;
    }

    const int pix = t & 63, grp = t >> 6;          // grp 0..3 -> 16 oc each
    const int px = pix & 7, py = pix >> 3;

    float acc[16][2][2];
#pragma unroll
    for (int i = 0; i < 16; i++) {
        acc[i][0][0] = 0.f; acc[i][0][1] = 0.f;
        acc[i][1][0] = 0.f; acc[i][1][1] = 0.f;
    }

    const float* hb = g_h + (size_t)b * C1_ * 64 * 64;
    const int r0 = 32 * by - 1;
    const int c0 = 32 * bx - 1;

    for (int cc = 0; cc < 8; cc++) {               // 8 chunks of 4 input channels
        __syncthreads();
        // weights chunk, pre-scaled + padded
        for (int i = t; i < C2_ * 36; i += 256) {
            int oc = i / 36, rem = i % 36;
            int cil = rem / 9, k = rem % 9;
            int ky = k / 3, kx = k % 3;
            s_w[oc * 48 + cil * 12 + ky * 4 + kx] =
                w2[oc * C1_ * 9 + (cc * 4 + cil) * 9 + k] * s_scale[oc];
        }
        // input chunk: 4 x 33x33 with zero halo
        for (int i = t; i < 4 * 33 * 33; i += 256) {
            int cil = i / (33 * 33);
            int rem = i % (33 * 33);
            int r = rem / 33, c = rem % 33;
            int gr = r0 + r, gc = c0 + c;
            float v = 0.f;
            if (gr >= 0 && gr < 64 && gc >= 0 && gc < 64)
                v = hb[(cc * 4 + cil) * 64 * 64 + gr * 64 + gc];
            s_in[cil][r][c] = v;
        }
        __syncthreads();

#pragma unroll
        for (int cil = 0; cil < 4; cil++) {
            // 5x5 patch: rows 4py+r, cols 4px..4px+4 (4px -> 16B aligned)
            float p[5][5];
#pragma unroll
            for (int r = 0; r < 5; r++) {
                float4 v4 = *(const float4*)&s_in[cil][4 * py + r][4 * px];
                p[r][0] = v4.x; p[r][1] = v4.y; p[r][2] = v4.z; p[r][3] = v4.w;
                p[r][4] = s_in[cil][4 * py + r][4 * px + 4];
            }

#pragma unroll
            for (int oc = 0; oc < 16; oc++) {
                const float4* w4 = (const float4*)&s_w[(grp * 16 + oc) * 48 + cil * 12];
#pragma unroll
                for (int ky = 0; ky < 3; ky++) {
                    float4 w = w4[ky];             // LDS.128
                    acc[oc][0][0] = fmaf(p[ky    ][0], w.x, acc[oc][0][0]);
                    acc[oc][0][1] = fmaf(p[ky    ][2], w.x, acc[oc][0][1]);
                    acc[oc][1][0] = fmaf(p[ky + 2][0], w.x, acc[oc][1][0]);
                    acc[oc][1][1] = fmaf(p[ky + 2][2], w.x, acc[oc][1][1]);
                    acc[oc][0][0] = fmaf(p[ky    ][1], w.y, acc[oc][0][0]);
                    acc[oc][0][1] = fmaf(p[ky    ][3], w.y, acc[oc][0][1]);
                    acc[oc][1][0] = fmaf(p[ky + 2][1], w.y, acc[oc][1][0]);
                    acc[oc][1][1] = fmaf(p[ky + 2][3], w.y, acc[oc][1][1]);
                    acc[oc][0][0] = fmaf(p[ky    ][2], w.z, acc[oc][0][0]);
                    acc[oc][0][1] = fmaf(p[ky    ][4], w.z, acc[oc][0][1]);
                    acc[oc][1][0] = fmaf(p[ky + 2][2], w.z, acc[oc][1][0]);
                    acc[oc][1][1] = fmaf(p[ky + 2][4], w.z, acc[oc][1][1]);
                }
            }
        }
    }

    // Epilogue: max-pool -> +bias -> sigmoid (conv pre-scaled; scale>0)
    const int oy = by * 8 + py, ox = bx * 8 + px;
    float* fb = feat + (size_t)b * C2_ * 16 * 16;
#pragma unroll
    for (int oc = 0; oc < 16; oc++) {
        int c = grp * 16 + oc;
        float m = fmaxf(fmaxf(acc[oc][0][0], acc[oc][0][1]),
                        fmaxf(acc[oc][1][0], acc[oc][1][1]));
        float v = m + s_bias[c];
        fb[c * 256 + oy * 16 + ox] = 1.f / (1.f + __expf(-v));
    }
}

// ---------------------------------------------------------------------------
// Kernel 3: per-image mean over feat [64,16,16] -> scores + detected
// ---------------------------------------------------------------------------
__global__ void __launch_bounds__(256) score_reduce(
    const float* __restrict__ feat,
    float* __restrict__ scores,
    float* __restrict__ detected)
{
    const int b = blockIdx.x;
    const float4* fb = (const float4*)(feat + (size_t)b * 16384);
    float s = 0.f;
    for (int i = threadIdx.x; i < 4096; i += 256) {
        float4 v = fb[i];
        s += (v.x + v.y) + (v.z + v.w);
    }

    __shared__ float red[8];
#pragma unroll
    for (int o = 16; o > 0; o >>= 1) s += __shfl_down_sync(0xffffffffu, s, o);
    if ((threadIdx.x & 31) == 0) red[threadIdx.x >> 5] = s;
    __syncthreads();
    if (threadIdx.x < 8) {
        s = red[threadIdx.x];
#pragma unroll
        for (int o = 4; o > 0; o >>= 1) s += __shfl_down_sync(0xffu, s, o);
        if (threadIdx.x == 0) {
            float sc = s * (1.f / 16384.f);
            scores[b]   = sc;
            detected[b] = (sc >= 0.55f) ? 1.f : 0.f;
        }
    }
}

// ---------------------------------------------------------------------------
extern "C" void kernel_launch(void* const* d_in, const int* in_sizes, int n_in,
                              void* d_out, int out_size)
{
    const float* crops = (const float*)d_in[0];
    const float* w1  = (const float*)d_in[1];
    const float* b1  = (const float*)d_in[2];
    const float* g1  = (const float*)d_in[3];
    const float* be1 = (const float*)d_in[4];
    const float* m1  = (const float*)d_in[5];
    const float* v1  = (const float*)d_in[6];
    const float* w2  = (const float*)d_in[7];
    const float* b2  = (const float*)d_in[8];
    const float* g2  = (const float*)d_in[9];
    const float* be2 = (const float*)d_in[10];
    const float* m2  = (const float*)d_in[11];
    const float* v2  = (const float*)d_in[12];

    float* out      = (float*)d_out;
    float* feat     = out;                                   // 512*64*16*16
    float* scores   = out + (size_t)B_ * C2_ * 16 * 16;      // +512
    float* detected = scores + B_;                           // +512

    conv1_fused<<<dim3(4, 4, B_), 256>>>(crops, w1, b1, g1, be1, m1, v1);
    conv2_fused<<<dim3(2, 2, B_), 256>>>(w2, b2, g2, be2, m2, v2, feat);
    score_reduce<<<B_, 256>>>(feat, scores, detected);
}